// round 1
// baseline (speedup 1.0000x reference)
#include <cuda_runtime.h>
#include <math.h>

// ---------------- problem constants ----------------
#define R_RAYS      4096
#define S_SAMPLES   32
#define RS_TOTAL    131072      // 4096*32
#define M_SAMPLES   6
#define NUM_LEVELS  10
#define LEVEL_DIM   4
#define FEAT_DIM    40          // NUM_LEVELS*LEVEL_DIM
#define HASHMASK    2097151u    // 2^21 - 1
#define RGB_ELEMS   393216      // RS_TOTAL*3

// level metadata (computed from the reference _level_meta())
__constant__ int c_offsets[NUM_LEVELS] = {
    0, 4920, 40864, 315496, 2412648, 4509800, 6606952, 8704104, 10801256, 12898408
};
__constant__ int c_sizes[NUM_LEVELS] = {
    4920, 35944, 274632, 2097152, 2097152, 2097152, 2097152, 2097152, 2097152, 2097152
};

// scratch: feat[rs][level*4+ch], fp32
__device__ float g_feat[RS_TOTAL * FEAT_DIM];

// ---------------- kernel 1: hash-grid encode ----------------
// thread = one (rs, level). Loops M=6 samples, 8 corners each.
__global__ __launch_bounds__(128) void grid_encode_kernel(
    const float* __restrict__ means,   // [RS_TOTAL, M, 3]
    const float* __restrict__ stds,    // [RS_TOTAL, M]
    const float4* __restrict__ table)  // [TOTAL_PARAMS] float4 rows
{
    int rs = blockIdx.x * blockDim.x + threadIdx.x;
    int level = blockIdx.y;
    if (rs >= RS_TOTAL) return;

    const float scale = (float)(16 << level);
    const unsigned res = (unsigned)((16 << level) + 1);
    const bool dense = (level < 3);
    const int off = c_offsets[level];
    const unsigned size_m1 = (unsigned)(c_sizes[level] - 1);

    float acc0 = 0.f, acc1 = 0.f, acc2 = 0.f, acc3 = 0.f;

    #pragma unroll 1
    for (int m = 0; m < M_SAMPLES; m++) {
        const int pidx = rs * M_SAMPLES + m;
        const float mx = means[pidx * 3 + 0];
        const float my = means[pidx * 3 + 1];
        const float mz = means[pidx * 3 + 2];
        const float sd = stds[pidx];

        // erf(1/sqrt(8*std^2*scale^2))
        const float wl = erff(1.0f / (2.8284271247461903f * sd * scale));

        float px = (mx + 1.0f) * 0.5f * scale + 0.5f;
        float py = (my + 1.0f) * 0.5f * scale + 0.5f;
        float pz = (mz + 1.0f) * 0.5f * scale + 0.5f;
        float f0x = floorf(px), f0y = floorf(py), f0z = floorf(pz);
        float fx = px - f0x, fy = py - f0y, fz = pz - f0z;
        unsigned ux = (unsigned)f0x, uy = (unsigned)f0y, uz = (unsigned)f0z;

        #pragma unroll
        for (int c = 0; c < 8; c++) {
            const unsigned bx = c & 1u;
            const unsigned by = (c >> 1) & 1u;
            const unsigned bz = (c >> 2) & 1u;
            const unsigned cx = ux + bx, cy = uy + by, cz = uz + bz;
            unsigned idx;
            if (dense) {
                idx = (cx * res + cy) * res + cz;
                idx = min(idx, size_m1);           // JAX gather clamps OOB
            } else {
                idx = (cx * 1u) ^ (cy * 2654435761u) ^ (cz * 805459861u);
                idx &= HASHMASK;
            }
            const float wx = bx ? fx : (1.0f - fx);
            const float wy = by ? fy : (1.0f - fy);
            const float wz = bz ? fz : (1.0f - fz);
            const float w = wx * wy * wz * wl;
            const float4 t = __ldg(table + off + (int)idx);
            acc0 += w * t.x;
            acc1 += w * t.y;
            acc2 += w * t.z;
            acc3 += w * t.w;
        }
    }
    const float inv = 1.0f / 6.0f;
    float4 o = make_float4(acc0 * inv, acc1 * inv, acc2 * inv, acc3 * inv);
    *(float4*)&g_feat[rs * FEAT_DIM + level * 4] = o;
}

// ---------------- kernel 2: fused MLP ----------------
// One CTA = RB rows of (R,S). 256 threads, thread = output channel.
#define RB 16

__global__ __launch_bounds__(256) void mlp_kernel(
    const float* __restrict__ vd,     // [R,3]
    const float* __restrict__ dw1,    // [40,64]
    const float* __restrict__ db1,    // [64]
    const float* __restrict__ dw2,    // [64,256]
    const float* __restrict__ db2,    // [256]
    const float* __restrict__ vw0,    // [283,256]
    const float* __restrict__ vb0,    // [256]
    const float* __restrict__ vw1,    // [539,256]
    const float* __restrict__ vb1,    // [256]
    const float* __restrict__ rw,     // [256,3]
    const float* __restrict__ rb,     // [3]
    float* __restrict__ out)          // [RGB_ELEMS + RS_TOTAL]
{
    __shared__ float feat_s[RB][FEAT_DIM];
    __shared__ float h_s[RB][64];
    __shared__ float inp_s[RB][256];   // x (layer2 output incl. bias)
    __shared__ float h2_s[RB][256];    // h2, later reused for h3
    __shared__ float dir_s[27];

    const int t = threadIdx.x;
    const int rs0 = blockIdx.x * RB;

    // load features
    #pragma unroll
    for (int i = t; i < RB * FEAT_DIM; i += 256) {
        feat_s[i / FEAT_DIM][i % FEAT_DIM] = g_feat[rs0 * FEAT_DIM + i];
    }

    // direction encoding (shared across the whole block: 16 rows < one ray's 32)
    const int ray = rs0 / S_SAMPLES;
    if (t < 27) {
        float v;
        if (t < 3) {
            v = vd[ray * 3 + t];
        } else {
            const int j = (t < 15) ? (t - 3) : (t - 15);
            const float x = vd[ray * 3 + (j % 3)];
            const float sc = (float)(1 << (j / 3));
            v = (t < 15) ? sinf(x * sc) : cosf(x * sc);
        }
        dir_s[t] = v;
    }
    __syncthreads();

    // ---- layer 1: 40 -> 64, relu ----
    {
        const int ch = t & 63;
        const int rg = t >> 6;                   // 4 groups x 4 rows
        float a0 = 0.f, a1 = 0.f, a2 = 0.f, a3 = 0.f;
        #pragma unroll 4
        for (int k = 0; k < FEAT_DIM; k++) {
            const float w = dw1[k * 64 + ch];
            a0 += feat_s[rg * 4 + 0][k] * w;
            a1 += feat_s[rg * 4 + 1][k] * w;
            a2 += feat_s[rg * 4 + 2][k] * w;
            a3 += feat_s[rg * 4 + 3][k] * w;
        }
        const float b = db1[ch];
        h_s[rg * 4 + 0][ch] = fmaxf(a0 + b, 0.f);
        h_s[rg * 4 + 1][ch] = fmaxf(a1 + b, 0.f);
        h_s[rg * 4 + 2][ch] = fmaxf(a2 + b, 0.f);
        h_s[rg * 4 + 3][ch] = fmaxf(a3 + b, 0.f);
    }
    __syncthreads();

    // ---- layer 2: 64 -> 256 (no relu) ----
    {
        const int ch = t;
        float acc[RB];
        #pragma unroll
        for (int r = 0; r < RB; r++) acc[r] = 0.f;
        #pragma unroll 4
        for (int k = 0; k < 64; k++) {
            const float w = dw2[k * 256 + ch];
            #pragma unroll
            for (int r = 0; r < RB; r++) acc[r] += h_s[r][k] * w;
        }
        const float b = db2[ch];
        #pragma unroll
        for (int r = 0; r < RB; r++) inp_s[r][ch] = acc[r] + b;
    }
    __syncthreads();

    // density = softplus(x[...,0] - 1)
    if (t < RB) {
        const float v = inp_s[t][0] - 1.0f;
        const float sp = fmaxf(v, 0.f) + log1pf(expf(-fabsf(v)));
        out[RGB_ELEMS + rs0 + t] = sp;
    }

    // ---- layer 3: [x(256), dir(27)] -> 256, relu ----
    {
        const int ch = t;
        float acc[RB];
        #pragma unroll
        for (int r = 0; r < RB; r++) acc[r] = 0.f;
        #pragma unroll 4
        for (int k = 0; k < 256; k++) {
            const float w = vw0[k * 256 + ch];
            #pragma unroll
            for (int r = 0; r < RB; r++) acc[r] += inp_s[r][k] * w;
        }
        // dir part identical for all rows in block -> scalar
        float dsum = 0.f;
        #pragma unroll
        for (int j = 0; j < 27; j++) dsum += dir_s[j] * vw0[(256 + j) * 256 + ch];
        const float b = vb0[ch] + dsum;
        #pragma unroll
        for (int r = 0; r < RB; r++) h2_s[r][ch] = fmaxf(acc[r] + b, 0.f);
    }
    __syncthreads();

    // ---- layer 4: [h2(256), x(256), dir(27)] -> 256, relu ----
    {
        const int ch = t;
        float acc[RB];
        #pragma unroll
        for (int r = 0; r < RB; r++) acc[r] = 0.f;
        #pragma unroll 4
        for (int k = 0; k < 256; k++) {
            const float w = vw1[k * 256 + ch];
            #pragma unroll
            for (int r = 0; r < RB; r++) acc[r] += h2_s[r][k] * w;
        }
        #pragma unroll 4
        for (int k = 0; k < 256; k++) {
            const float w = vw1[(256 + k) * 256 + ch];
            #pragma unroll
            for (int r = 0; r < RB; r++) acc[r] += inp_s[r][k] * w;
        }
        float dsum = 0.f;
        #pragma unroll
        for (int j = 0; j < 27; j++) dsum += dir_s[j] * vw1[(512 + j) * 256 + ch];
        const float b = vb1[ch] + dsum;
        __syncthreads();   // done reading h2_s; safe to overwrite with h3
        #pragma unroll
        for (int r = 0; r < RB; r++) h2_s[r][ch] = fmaxf(acc[r] + b, 0.f);
    }
    __syncthreads();

    // ---- rgb head: 256 -> 3, sigmoid, affine ----
    {
        const int warp = t >> 5, lane = t & 31;
        for (int q = warp; q < RB * 3; q += 8) {
            const int r = q / 3, ch = q % 3;
            float s = 0.f;
            #pragma unroll 4
            for (int k = lane; k < 256; k += 32) s += h2_s[r][k] * rw[k * 3 + ch];
            #pragma unroll
            for (int o = 16; o > 0; o >>= 1) s += __shfl_down_sync(0xffffffffu, s, o);
            if (lane == 0) {
                const float sig = 1.0f / (1.0f + expf(-(s + rb[ch])));
                out[(rs0 + r) * 3 + ch] = sig * 1.002f - 0.001f;
            }
        }
    }
}

// ---------------- launch ----------------
extern "C" void kernel_launch(void* const* d_in, const int* in_sizes, int n_in,
                              void* d_out, int out_size)
{
    const float* means = (const float*)d_in[0];
    const float* stds  = (const float*)d_in[1];
    const float* vd    = (const float*)d_in[2];
    const float* table = (const float*)d_in[3];
    const float* dw1   = (const float*)d_in[4];
    const float* db1   = (const float*)d_in[5];
    const float* dw2   = (const float*)d_in[6];
    const float* db2   = (const float*)d_in[7];
    const float* vw0   = (const float*)d_in[8];
    const float* vb0   = (const float*)d_in[9];
    const float* vw1   = (const float*)d_in[10];
    const float* vb1   = (const float*)d_in[11];
    const float* rw    = (const float*)d_in[12];
    const float* rb    = (const float*)d_in[13];
    float* out = (float*)d_out;

    dim3 g1((RS_TOTAL + 127) / 128, NUM_LEVELS);
    grid_encode_kernel<<<g1, 128>>>(means, stds, (const float4*)table);

    mlp_kernel<<<RS_TOTAL / RB, 256>>>(vd, dw1, db1, dw2, db2,
                                       vw0, vb0, vw1, vb1, rw, rb, out);
}

// round 2
// speedup vs baseline: 1.4021x; 1.4021x over previous
#include <cuda_runtime.h>
#include <math.h>

// ---------------- problem constants ----------------
#define R_RAYS      4096
#define S_SAMPLES   32
#define RS_TOTAL    131072
#define M_SAMPLES   6
#define NUM_LEVELS  10
#define LEVEL_DIM   4
#define FEAT_DIM    40
#define HASHMASK    2097151u
#define RGB_ELEMS   393216

__constant__ int c_offsets[NUM_LEVELS] = {
    0, 4920, 40864, 315496, 2412648, 4509800, 6606952, 8704104, 10801256, 12898408
};
__constant__ int c_sizes[NUM_LEVELS] = {
    4920, 35944, 274632, 2097152, 2097152, 2097152, 2097152, 2097152, 2097152, 2097152
};

__device__ float g_feat[RS_TOTAL * FEAT_DIM];

// ---------------- packed f32x2 helpers ----------------
typedef unsigned long long u64;
__device__ __forceinline__ void ffma2(u64 &d, u64 a, u64 b) {
    asm("fma.rn.f32x2 %0, %1, %2, %0;" : "+l"(d) : "l"(a), "l"(b));
}
__device__ __forceinline__ u64 dup2(float x) {
    u64 r; asm("mov.b64 %0, {%1, %1};" : "=l"(r) : "f"(x)); return r;
}
__device__ __forceinline__ float2 unpk(u64 v) {
    float2 r; asm("mov.b64 {%0, %1}, %2;" : "=f"(r.x), "=f"(r.y) : "l"(v)); return r;
}

// ---------------- kernel 1: hash-grid encode (unchanged, passed) ----------------
__global__ __launch_bounds__(128) void grid_encode_kernel(
    const float* __restrict__ means,
    const float* __restrict__ stds,
    const float4* __restrict__ table)
{
    int rs = blockIdx.x * blockDim.x + threadIdx.x;
    int level = blockIdx.y;
    if (rs >= RS_TOTAL) return;

    const float scale = (float)(16 << level);
    const unsigned res = (unsigned)((16 << level) + 1);
    const bool dense = (level < 3);
    const int off = c_offsets[level];
    const unsigned size_m1 = (unsigned)(c_sizes[level] - 1);

    float acc0 = 0.f, acc1 = 0.f, acc2 = 0.f, acc3 = 0.f;

    #pragma unroll 1
    for (int m = 0; m < M_SAMPLES; m++) {
        const int pidx = rs * M_SAMPLES + m;
        const float mx = means[pidx * 3 + 0];
        const float my = means[pidx * 3 + 1];
        const float mz = means[pidx * 3 + 2];
        const float sd = stds[pidx];

        const float wl = erff(1.0f / (2.8284271247461903f * sd * scale));

        float px = (mx + 1.0f) * 0.5f * scale + 0.5f;
        float py = (my + 1.0f) * 0.5f * scale + 0.5f;
        float pz = (mz + 1.0f) * 0.5f * scale + 0.5f;
        float f0x = floorf(px), f0y = floorf(py), f0z = floorf(pz);
        float fx = px - f0x, fy = py - f0y, fz = pz - f0z;
        unsigned ux = (unsigned)f0x, uy = (unsigned)f0y, uz = (unsigned)f0z;

        #pragma unroll
        for (int c = 0; c < 8; c++) {
            const unsigned bx = c & 1u;
            const unsigned by = (c >> 1) & 1u;
            const unsigned bz = (c >> 2) & 1u;
            const unsigned cx = ux + bx, cy = uy + by, cz = uz + bz;
            unsigned idx;
            if (dense) {
                idx = (cx * res + cy) * res + cz;
                idx = min(idx, size_m1);
            } else {
                idx = (cx * 1u) ^ (cy * 2654435761u) ^ (cz * 805459861u);
                idx &= HASHMASK;
            }
            const float wx = bx ? fx : (1.0f - fx);
            const float wy = by ? fy : (1.0f - fy);
            const float wz = bz ? fz : (1.0f - fz);
            const float w = wx * wy * wz * wl;
            const float4 tt = __ldg(table + off + (int)idx);
            acc0 += w * tt.x;
            acc1 += w * tt.y;
            acc2 += w * tt.z;
            acc3 += w * tt.w;
        }
    }
    const float inv = 1.0f / 6.0f;
    float4 o = make_float4(acc0 * inv, acc1 * inv, acc2 * inv, acc3 * inv);
    *(float4*)&g_feat[rs * FEAT_DIM + level * 4] = o;
}

// ---------------- kernel 2: fused MLP, packed f32x2, transposed smem ----------------
#define RB 16
#define H2S 20   // padded row stride for h2/h3 buffer (16B-aligned, 4-way head conflicts)

__global__ __launch_bounds__(256, 3) void mlp_kernel(
    const float* __restrict__ vd,
    const float* __restrict__ dw1,
    const float* __restrict__ db1,
    const float* __restrict__ dw2,
    const float* __restrict__ db2,
    const float* __restrict__ vw0,
    const float* __restrict__ vb0,
    const float* __restrict__ vw1,
    const float* __restrict__ vb1,
    const float* __restrict__ rw,
    const float* __restrict__ rbias,
    float* __restrict__ out)
{
    __shared__ __align__(16) float feat_t[FEAT_DIM][RB];  // k-major
    __shared__ __align__(16) float h_t[64][RB];
    __shared__ __align__(16) float x_t[256][RB];
    __shared__ __align__(16) float h2_t[256][H2S];        // h2, then reused for h3
    __shared__ float dir_s[27];

    const int t = threadIdx.x;
    const int rs0 = blockIdx.x * RB;

    // load + transpose features
    for (int i = t; i < RB * FEAT_DIM; i += 256) {
        const int r = i / FEAT_DIM, k = i % FEAT_DIM;
        feat_t[k][r] = g_feat[rs0 * FEAT_DIM + i];
    }

    // direction encoding (one ray covers these 16 rows: 16 < 32 samples/ray)
    const int ray = rs0 / S_SAMPLES;
    if (t < 27) {
        float v;
        if (t < 3) {
            v = vd[ray * 3 + t];
        } else {
            const int j = (t < 15) ? (t - 3) : (t - 15);
            const float x = vd[ray * 3 + (j % 3)];
            const float sc = (float)(1 << (j / 3));
            v = (t < 15) ? sinf(x * sc) : cosf(x * sc);
        }
        dir_s[t] = v;
    }
    __syncthreads();

    // ---- layer 1: 40 -> 64, relu.  256 thr = 64 ch x 4 row-groups(4 rows) ----
    {
        const int ch = t & 63;
        const int rg = t >> 6;
        u64 a0 = 0, a1 = 0;
        #pragma unroll 4
        for (int k = 0; k < FEAT_DIM; k++) {
            const ulonglong2 p = *(const ulonglong2*)&feat_t[k][rg * 4];
            const u64 w = dup2(dw1[k * 64 + ch]);
            ffma2(a0, p.x, w);
            ffma2(a1, p.y, w);
        }
        const float b = db1[ch];
        const float2 v0 = unpk(a0), v1 = unpk(a1);
        *(float2*)&h_t[ch][rg * 4]     = make_float2(fmaxf(v0.x + b, 0.f), fmaxf(v0.y + b, 0.f));
        *(float2*)&h_t[ch][rg * 4 + 2] = make_float2(fmaxf(v1.x + b, 0.f), fmaxf(v1.y + b, 0.f));
    }
    __syncthreads();

    // mapping for 256-wide layers: 2 channels/thread, rows split in halves of 8
    const int half = t >> 7;          // 0: rows 0-7, 1: rows 8-15
    const int tc = t & 127;
    const int ch0 = tc * 2;
    const int rbase = half * 8;

    // ---- layer 2: 64 -> 256 (no relu) ----
    {
        u64 A[4] = {0,0,0,0}, B[4] = {0,0,0,0};
        #pragma unroll 2
        for (int k = 0; k < 64; k++) {
            const ulonglong2 pA = *(const ulonglong2*)&h_t[k][rbase];
            const ulonglong2 pB = *(const ulonglong2*)&h_t[k][rbase + 4];
            const float2 w = *(const float2*)&dw2[k * 256 + ch0];
            const u64 w0 = dup2(w.x), w1 = dup2(w.y);
            ffma2(A[0], pA.x, w0); ffma2(A[1], pA.y, w0);
            ffma2(A[2], pB.x, w0); ffma2(A[3], pB.y, w0);
            ffma2(B[0], pA.x, w1); ffma2(B[1], pA.y, w1);
            ffma2(B[2], pB.x, w1); ffma2(B[3], pB.y, w1);
        }
        const float2 b = *(const float2*)&db2[ch0];
        #pragma unroll
        for (int i = 0; i < 4; i++) {
            const float2 va = unpk(A[i]);
            *(float2*)&x_t[ch0][rbase + 2 * i]     = make_float2(va.x + b.x, va.y + b.x);
            const float2 vb = unpk(B[i]);
            *(float2*)&x_t[ch0 + 1][rbase + 2 * i] = make_float2(vb.x + b.y, vb.y + b.y);
        }
    }
    __syncthreads();

    // density = softplus(x[...,0] - 1)
    if (t < RB) {
        const float v = x_t[0][t] - 1.0f;
        out[RGB_ELEMS + rs0 + t] = fmaxf(v, 0.f) + log1pf(expf(-fabsf(v)));
    }

    // ---- layer 3: [x(256), dir(27)] -> 256, relu ----
    {
        u64 A[4] = {0,0,0,0}, B[4] = {0,0,0,0};
        #pragma unroll 2
        for (int k = 0; k < 256; k++) {
            const ulonglong2 pA = *(const ulonglong2*)&x_t[k][rbase];
            const ulonglong2 pB = *(const ulonglong2*)&x_t[k][rbase + 4];
            const float2 w = *(const float2*)&vw0[k * 256 + ch0];
            const u64 w0 = dup2(w.x), w1 = dup2(w.y);
            ffma2(A[0], pA.x, w0); ffma2(A[1], pA.y, w0);
            ffma2(A[2], pB.x, w0); ffma2(A[3], pB.y, w0);
            ffma2(B[0], pA.x, w1); ffma2(B[1], pA.y, w1);
            ffma2(B[2], pB.x, w1); ffma2(B[3], pB.y, w1);
        }
        float d0 = 0.f, d1 = 0.f;
        #pragma unroll
        for (int j = 0; j < 27; j++) {
            const float2 w = *(const float2*)&vw0[(256 + j) * 256 + ch0];
            d0 += dir_s[j] * w.x;
            d1 += dir_s[j] * w.y;
        }
        const float2 b = *(const float2*)&vb0[ch0];
        const float b0 = b.x + d0, b1 = b.y + d1;
        #pragma unroll
        for (int i = 0; i < 4; i++) {
            const float2 va = unpk(A[i]);
            h2_t[ch0][rbase + 2 * i]     = fmaxf(va.x + b0, 0.f);
            h2_t[ch0][rbase + 2 * i + 1] = fmaxf(va.y + b0, 0.f);
            const float2 vb = unpk(B[i]);
            h2_t[ch0 + 1][rbase + 2 * i]     = fmaxf(vb.x + b1, 0.f);
            h2_t[ch0 + 1][rbase + 2 * i + 1] = fmaxf(vb.y + b1, 0.f);
        }
    }
    __syncthreads();

    // ---- layer 4: [h2(256), x(256), dir(27)] -> 256, relu; writes h3 over h2_t ----
    {
        u64 A[4] = {0,0,0,0}, B[4] = {0,0,0,0};
        #pragma unroll 2
        for (int k = 0; k < 256; k++) {
            const ulonglong2 pA = *(const ulonglong2*)&h2_t[k][rbase];
            const ulonglong2 pB = *(const ulonglong2*)&h2_t[k][rbase + 4];
            const float2 w = *(const float2*)&vw1[k * 256 + ch0];
            const u64 w0 = dup2(w.x), w1 = dup2(w.y);
            ffma2(A[0], pA.x, w0); ffma2(A[1], pA.y, w0);
            ffma2(A[2], pB.x, w0); ffma2(A[3], pB.y, w0);
            ffma2(B[0], pA.x, w1); ffma2(B[1], pA.y, w1);
            ffma2(B[2], pB.x, w1); ffma2(B[3], pB.y, w1);
        }
        #pragma unroll 2
        for (int k = 0; k < 256; k++) {
            const ulonglong2 pA = *(const ulonglong2*)&x_t[k][rbase];
            const ulonglong2 pB = *(const ulonglong2*)&x_t[k][rbase + 4];
            const float2 w = *(const float2*)&vw1[(256 + k) * 256 + ch0];
            const u64 w0 = dup2(w.x), w1 = dup2(w.y);
            ffma2(A[0], pA.x, w0); ffma2(A[1], pA.y, w0);
            ffma2(A[2], pB.x, w0); ffma2(A[3], pB.y, w0);
            ffma2(B[0], pA.x, w1); ffma2(B[1], pA.y, w1);
            ffma2(B[2], pB.x, w1); ffma2(B[3], pB.y, w1);
        }
        float d0 = 0.f, d1 = 0.f;
        #pragma unroll
        for (int j = 0; j < 27; j++) {
            const float2 w = *(const float2*)&vw1[(512 + j) * 256 + ch0];
            d0 += dir_s[j] * w.x;
            d1 += dir_s[j] * w.y;
        }
        const float2 b = *(const float2*)&vb1[ch0];
        const float b0 = b.x + d0, b1 = b.y + d1;

        __syncthreads();   // everyone done READING h2_t; safe to overwrite with h3
        #pragma unroll
        for (int i = 0; i < 4; i++) {
            const float2 va = unpk(A[i]);
            h2_t[ch0][rbase + 2 * i]     = fmaxf(va.x + b0, 0.f);
            h2_t[ch0][rbase + 2 * i + 1] = fmaxf(va.y + b0, 0.f);
            const float2 vb = unpk(B[i]);
            h2_t[ch0 + 1][rbase + 2 * i]     = fmaxf(vb.x + b1, 0.f);
            h2_t[ch0 + 1][rbase + 2 * i + 1] = fmaxf(vb.y + b1, 0.f);
        }
    }
    __syncthreads();

    // ---- rgb head: 256 -> 3, sigmoid, affine ----
    {
        const int warp = t >> 5, lane = t & 31;
        for (int q = warp; q < RB * 3; q += 8) {
            const int r = q / 3, c = q % 3;
            float s = 0.f;
            #pragma unroll
            for (int k = lane; k < 256; k += 32) s += h2_t[k][r] * rw[k * 3 + c];
            #pragma unroll
            for (int o = 16; o > 0; o >>= 1) s += __shfl_down_sync(0xffffffffu, s, o);
            if (lane == 0) {
                const float sig = 1.0f / (1.0f + expf(-(s + rbias[c])));
                out[(rs0 + r) * 3 + c] = sig * 1.002f - 0.001f;
            }
        }
    }
}

// ---------------- launch ----------------
extern "C" void kernel_launch(void* const* d_in, const int* in_sizes, int n_in,
                              void* d_out, int out_size)
{
    const float* means = (const float*)d_in[0];
    const float* stds  = (const float*)d_in[1];
    const float* vd    = (const float*)d_in[2];
    const float* table = (const float*)d_in[3];
    const float* dw1   = (const float*)d_in[4];
    const float* db1   = (const float*)d_in[5];
    const float* dw2   = (const float*)d_in[6];
    const float* db2   = (const float*)d_in[7];
    const float* vw0   = (const float*)d_in[8];
    const float* vb0   = (const float*)d_in[9];
    const float* vw1   = (const float*)d_in[10];
    const float* vb1   = (const float*)d_in[11];
    const float* rw    = (const float*)d_in[12];
    const float* rb    = (const float*)d_in[13];
    float* out = (float*)d_out;

    dim3 g1((RS_TOTAL + 127) / 128, NUM_LEVELS);
    grid_encode_kernel<<<g1, 128>>>(means, stds, (const float4*)table);

    mlp_kernel<<<RS_TOTAL / RB, 256>>>(vd, dw1, db1, dw2, db2,
                                       vw0, vb0, vw1, vb1, rw, rb, out);
}

// round 4
// speedup vs baseline: 5.6292x; 4.0149x over previous
#include <cuda_runtime.h>
#include <cuda_fp16.h>
#include <math.h>
#include <stdint.h>

// ---------------- problem constants ----------------
#define R_RAYS      4096
#define S_SAMPLES   32
#define RS_TOTAL    131072
#define M_SAMPLES   6
#define NUM_LEVELS  10
#define FEAT_DIM    40
#define HASHMASK    2097151u
#define RGB_ELEMS   393216

__constant__ int c_offsets[NUM_LEVELS] = {
    0, 4920, 40864, 315496, 2412648, 4509800, 6606952, 8704104, 10801256, 12898408
};
__constant__ int c_sizes[NUM_LEVELS] = {
    4920, 35944, 274632, 2097152, 2097152, 2097152, 2097152, 2097152, 2097152, 2097152
};

__device__ float g_feat[RS_TOTAL * FEAT_DIM];

// packed fp16 weight fragments for all 4 layers, laid out contiguously.
// half2 layout index = ((kt*NP + np)*32 + lane)*4 + j
//   j=0: b0 of ntile np*2   (elements W[k][n], W[k+1][n])
//   j=1: b1 of ntile np*2   (k+8)
//   j=2: b0 of ntile np*2+1
//   j=3: b1 of ntile np*2+1
// layer bases (half2): L1=0(1536), L2=1536(8192), L3=9728(36864), L4=46592(69632)
#define PK_TOTAL_H2 116224
__device__ __align__(16) __half2 Wpk[PK_TOTAL_H2];

#define SLAB 568   // slab row stride in halves (1136B: conflict-free 8-row fragment loads)

// ---------------- mma helper ----------------
__device__ __forceinline__ void mma16816(float c[4],
    unsigned a0, unsigned a1, unsigned a2, unsigned a3,
    unsigned b0, unsigned b1)
{
    asm volatile(
        "mma.sync.aligned.m16n8k16.row.col.f32.f16.f16.f32 "
        "{%0,%1,%2,%3}, {%4,%5,%6,%7}, {%8,%9}, {%0,%1,%2,%3};"
        : "+f"(c[0]), "+f"(c[1]), "+f"(c[2]), "+f"(c[3])
        : "r"(a0), "r"(a1), "r"(a2), "r"(a3), "r"(b0), "r"(b1));
}

// ---------------- kernel 0: weight prep ----------------
__global__ __launch_bounds__(256) void prep_kernel(
    const float* __restrict__ dw1, const float* __restrict__ dw2,
    const float* __restrict__ vw0, const float* __restrict__ vw1)
{
    int idx = blockIdx.x * 256 + threadIdx.x;   // half2 index, 0..116223
    if (idx >= PK_TOTAL_H2) return;

    int local, NP, layer;
    if (idx < 1536)        { layer = 1; local = idx;         NP = 4;  }
    else if (idx < 9728)   { layer = 2; local = idx - 1536;  NP = 16; }
    else if (idx < 46592)  { layer = 3; local = idx - 9728;  NP = 16; }
    else                   { layer = 4; local = idx - 46592; NP = 16; }

    const int j    = local & 3;
    const int lane = (local >> 2) & 31;
    const int rem  = local >> 7;
    const int np   = rem % NP;
    const int kt   = rem / NP;

    const int nt  = np * 2 + (j >> 1);
    const int reg = j & 1;
    const int n   = nt * 8 + (lane >> 2);
    const int k   = kt * 16 + reg * 8 + (lane & 3) * 2;

    float v0 = 0.f, v1 = 0.f;
    if (layer == 1) {
        if (k     < 40) v0 = dw1[k * 64 + n];
        if (k + 1 < 40) v1 = dw1[(k + 1) * 64 + n];
    } else if (layer == 2) {
        v0 = dw2[k * 256 + n];
        v1 = dw2[(k + 1) * 256 + n];
    } else if (layer == 3) {
        if (k     < 283) v0 = vw0[k * 256 + n];
        if (k + 1 < 283) v1 = vw0[(k + 1) * 256 + n];
    } else {
        if (k     < 539) v0 = vw1[k * 256 + n];
        if (k + 1 < 539) v1 = vw1[(k + 1) * 256 + n];
    }
    Wpk[idx] = __floats2half2_rn(v0, v1);
}

// ---------------- kernel 1: hash-grid encode (validated R1/R2) ----------------
__global__ __launch_bounds__(128) void grid_encode_kernel(
    const float* __restrict__ means,
    const float* __restrict__ stds,
    const float4* __restrict__ table)
{
    int rs = blockIdx.x * blockDim.x + threadIdx.x;
    int level = blockIdx.y;
    if (rs >= RS_TOTAL) return;

    const float scale = (float)(16 << level);
    const unsigned res = (unsigned)((16 << level) + 1);
    const bool dense = (level < 3);
    const int off = c_offsets[level];
    const unsigned size_m1 = (unsigned)(c_sizes[level] - 1);

    float acc0 = 0.f, acc1 = 0.f, acc2 = 0.f, acc3 = 0.f;

    #pragma unroll 1
    for (int m = 0; m < M_SAMPLES; m++) {
        const int pidx = rs * M_SAMPLES + m;
        const float mx = means[pidx * 3 + 0];
        const float my = means[pidx * 3 + 1];
        const float mz = means[pidx * 3 + 2];
        const float sd = stds[pidx];
        const float wl = erff(1.0f / (2.8284271247461903f * sd * scale));

        float px = (mx + 1.0f) * 0.5f * scale + 0.5f;
        float py = (my + 1.0f) * 0.5f * scale + 0.5f;
        float pz = (mz + 1.0f) * 0.5f * scale + 0.5f;
        float f0x = floorf(px), f0y = floorf(py), f0z = floorf(pz);
        float fx = px - f0x, fy = py - f0y, fz = pz - f0z;
        unsigned ux = (unsigned)f0x, uy = (unsigned)f0y, uz = (unsigned)f0z;

        #pragma unroll
        for (int c = 0; c < 8; c++) {
            const unsigned bx = c & 1u, by = (c >> 1) & 1u, bz = (c >> 2) & 1u;
            const unsigned cx = ux + bx, cy = uy + by, cz = uz + bz;
            unsigned idx;
            if (dense) { idx = (cx * res + cy) * res + cz; idx = min(idx, size_m1); }
            else { idx = (cx * 1u) ^ (cy * 2654435761u) ^ (cz * 805459861u); idx &= HASHMASK; }
            const float wx = bx ? fx : (1.0f - fx);
            const float wy = by ? fy : (1.0f - fy);
            const float wz = bz ? fz : (1.0f - fz);
            const float w = wx * wy * wz * wl;
            const float4 tt = __ldg(table + off + (int)idx);
            acc0 += w * tt.x; acc1 += w * tt.y; acc2 += w * tt.z; acc3 += w * tt.w;
        }
    }
    const float inv = 1.0f / 6.0f;
    *(float4*)&g_feat[rs * FEAT_DIM + level * 4] =
        make_float4(acc0 * inv, acc1 * inv, acc2 * inv, acc3 * inv);
}

// ---------------- generic fragment-GEMM layer over the smem slab ----------------
// A: slab rows [mr..mr+15], cols [acol0 .. acol0+KT*16)
// B: packed fragments wpk (half2*), NP ntile-pairs total; this warp uses np in
//    [nh*NP/2, (nh+1)*NP/2) -> NTW ntiles, 8*NTW output channels at n-base nh*8*NTW.
template<int KT, int NTW, int NP>
__device__ __forceinline__ void run_layer(
    const __half* slab, int acol0, int mr, int gr, int gc,
    const __half2* __restrict__ wpk, int nh, int lane, float C[][4])
{
    const __half* arow = slab + (mr + gr) * SLAB + acol0 + gc * 2;
    const uint4* wbase = (const uint4*)wpk + (size_t)(nh * (NP / 2)) * 32 + lane;
    #pragma unroll 1
    for (int kt = 0; kt < KT; kt++) {
        const __half* ap = arow + kt * 16;
        unsigned a0 = *(const unsigned*)(ap);
        unsigned a2 = *(const unsigned*)(ap + 8);
        unsigned a1 = *(const unsigned*)(ap + 8 * SLAB);
        unsigned a3 = *(const unsigned*)(ap + 8 * SLAB + 8);
        const uint4* wp = wbase + (size_t)kt * NP * 32;
        #pragma unroll
        for (int p = 0; p < NTW / 2; p++) {
            uint4 b = __ldg(wp + p * 32);
            mma16816(C[2 * p],     a0, a1, a2, a3, b.x, b.y);
            mma16816(C[2 * p + 1], a0, a1, a2, a3, b.z, b.w);
        }
    }
}

// ---------------- kernel 2: fused MLP via mma.sync (fp16 in, fp32 accum) ----------------
// smem: slab 128x568 halves (145408B) | dirsm 128f | rwsm 768f | parth 768f
#define SM_DIR   145408
#define SM_RW    145920
#define SM_PARTH 148992
#define SM_TOTAL 152064

__global__ __launch_bounds__(512, 1) void mlp_mma_kernel(
    const float* __restrict__ vd,
    const float* __restrict__ db1, const float* __restrict__ db2,
    const float* __restrict__ vb0, const float* __restrict__ vb1,
    const float* __restrict__ rw,  const float* __restrict__ rbias,
    float* __restrict__ out)
{
    extern __shared__ char dyn[];
    __half* slab = (__half*)dyn;
    float* dirsm = (float*)(dyn + SM_DIR);
    float* rwsm  = (float*)(dyn + SM_RW);
    float* parth = (float*)(dyn + SM_PARTH);

    const int t = threadIdx.x;
    const int w = t >> 5, lane = t & 31;
    const int gr = lane >> 2, gc = lane & 3;
    const int mt = w & 7, nh = w >> 3;
    const int mr = mt * 16;
    const int rs0 = blockIdx.x * 128;

    // rw -> smem
    for (int i = t; i < 768; i += 512) rwsm[i] = rw[i];

    // dir encoding: 4 rays x 32 cols (cols >= 27 zero)
    if (t < 128) {
        int ray = t >> 5, c = t & 31;
        int rg = blockIdx.x * 4 + ray;
        float v = 0.f;
        if (c < 3) v = vd[rg * 3 + c];
        else if (c < 15) { int j = c - 3;  v = sinf(vd[rg * 3 + (j % 3)] * (float)(1 << (j / 3))); }
        else if (c < 27) { int j = c - 15; v = cosf(vd[rg * 3 + (j % 3)] * (float)(1 << (j / 3))); }
        dirsm[t] = v;
    }

    // feat -> slab cols 0..47 (40 real + 8 zero)
    for (int i = t; i < 128 * 48; i += 512) {
        int r = i / 48, c = i % 48;
        float v = (c < 40) ? g_feat[(rs0 + r) * FEAT_DIM + c] : 0.f;
        slab[r * SLAB + c] = __float2half_rn(v);
    }
    __syncthreads();

    // dir -> slab cols 512..543 (32 cols incl zero pad)
    {
        int r = t >> 2, c0 = (t & 3) * 8;
        const float* ds = &dirsm[(r >> 5) * 32];
        #pragma unroll
        for (int j = 0; j < 8; j++)
            slab[r * SLAB + 512 + c0 + j] = __float2half_rn(ds[c0 + j]);
    }

    // ---- L1: feat(cols 0..47) @ W1 -> h1 (relu) -> cols 64..127 ----
    {
        float C[4][4] = {};
        run_layer<3, 4, 4>(slab, 0, mr, gr, gc, Wpk, nh, lane, C);
        #pragma unroll
        for (int nt = 0; nt < 4; nt++) {
            int n = nh * 32 + nt * 8 + 2 * gc;
            float2 b = *(const float2*)&db1[n];
            __half2 lo = __floats2half2_rn(fmaxf(C[nt][0] + b.x, 0.f), fmaxf(C[nt][1] + b.y, 0.f));
            __half2 hi = __floats2half2_rn(fmaxf(C[nt][2] + b.x, 0.f), fmaxf(C[nt][3] + b.y, 0.f));
            *(__half2*)&slab[(mr + gr) * SLAB + 64 + n]     = lo;
            *(__half2*)&slab[(mr + gr + 8) * SLAB + 64 + n] = hi;
        }
    }
    __syncthreads();

    // ---- L2: h1(cols 64..127) @ W2 -> x (no relu) -> cols 256..511; density ----
    {
        float C[16][4] = {};
        run_layer<4, 16, 16>(slab, 64, mr, gr, gc, Wpk + 1536, nh, lane, C);
        if (nh == 0 && gc == 0) {
            float xa = C[0][0] + __ldg(&db2[0]) - 1.0f;
            float xb = C[0][2] + __ldg(&db2[0]) - 1.0f;
            out[RGB_ELEMS + rs0 + mr + gr]     = fmaxf(xa, 0.f) + log1pf(expf(-fabsf(xa)));
            out[RGB_ELEMS + rs0 + mr + gr + 8] = fmaxf(xb, 0.f) + log1pf(expf(-fabsf(xb)));
        }
        #pragma unroll
        for (int nt = 0; nt < 16; nt++) {
            int n = nh * 128 + nt * 8 + 2 * gc;
            float2 b = *(const float2*)&db2[n];
            __half2 lo = __floats2half2_rn(C[nt][0] + b.x, C[nt][1] + b.y);
            __half2 hi = __floats2half2_rn(C[nt][2] + b.x, C[nt][3] + b.y);
            *(__half2*)&slab[(mr + gr) * SLAB + 256 + n]     = lo;
            *(__half2*)&slab[(mr + gr + 8) * SLAB + 256 + n] = hi;
        }
    }
    __syncthreads();

    // ---- L3: [x|dir](cols 256..543) @ W3 -> h2 (relu) -> cols 0..255 ----
    {
        float C[16][4] = {};
        run_layer<18, 16, 16>(slab, 256, mr, gr, gc, Wpk + 9728, nh, lane, C);
        #pragma unroll
        for (int nt = 0; nt < 16; nt++) {
            int n = nh * 128 + nt * 8 + 2 * gc;
            float2 b = *(const float2*)&vb0[n];
            __half2 lo = __floats2half2_rn(fmaxf(C[nt][0] + b.x, 0.f), fmaxf(C[nt][1] + b.y, 0.f));
            __half2 hi = __floats2half2_rn(fmaxf(C[nt][2] + b.x, 0.f), fmaxf(C[nt][3] + b.y, 0.f));
            *(__half2*)&slab[(mr + gr) * SLAB + n]     = lo;
            *(__half2*)&slab[(mr + gr + 8) * SLAB + n] = hi;
        }
    }
    __syncthreads();

    // ---- L4: [h2|x|dir](cols 0..543) @ W4 -> h3 (relu, in regs) -> rgb head ----
    {
        float C[16][4] = {};
        run_layer<34, 16, 16>(slab, 0, mr, gr, gc, Wpk + 46592, nh, lane, C);

        float pl[3] = {0.f, 0.f, 0.f}, ph[3] = {0.f, 0.f, 0.f};
        #pragma unroll
        for (int nt = 0; nt < 16; nt++) {
            int n = nh * 128 + nt * 8 + 2 * gc;
            float2 b = *(const float2*)&vb1[n];
            float h0 = fmaxf(C[nt][0] + b.x, 0.f);
            float h1 = fmaxf(C[nt][1] + b.y, 0.f);
            float h2 = fmaxf(C[nt][2] + b.x, 0.f);
            float h3 = fmaxf(C[nt][3] + b.y, 0.f);
            #pragma unroll
            for (int j = 0; j < 3; j++) {
                pl[j] += h0 * rwsm[n * 3 + j] + h1 * rwsm[(n + 1) * 3 + j];
                ph[j] += h2 * rwsm[n * 3 + j] + h3 * rwsm[(n + 1) * 3 + j];
            }
        }
        #pragma unroll
        for (int j = 0; j < 3; j++) {
            pl[j] += __shfl_xor_sync(0xffffffffu, pl[j], 1);
            pl[j] += __shfl_xor_sync(0xffffffffu, pl[j], 2);
            ph[j] += __shfl_xor_sync(0xffffffffu, ph[j], 1);
            ph[j] += __shfl_xor_sync(0xffffffffu, ph[j], 2);
        }
        if (gc == 0) {
            #pragma unroll
            for (int j = 0; j < 3; j++) {
                parth[(mr + gr) * 6 + nh * 3 + j]     = pl[j];
                parth[(mr + gr + 8) * 6 + nh * 3 + j] = ph[j];
            }
        }
    }
    __syncthreads();

    if (t < 128) {
        #pragma unroll
        for (int j = 0; j < 3; j++) {
            float s = parth[t * 6 + j] + parth[t * 6 + 3 + j] + __ldg(&rbias[j]);
            float sig = 1.0f / (1.0f + expf(-s));
            out[(rs0 + t) * 3 + j] = sig * 1.002f - 0.001f;
        }
    }
}

// ---------------- launch ----------------
extern "C" void kernel_launch(void* const* d_in, const int* in_sizes, int n_in,
                              void* d_out, int out_size)
{
    const float* means = (const float*)d_in[0];
    const float* stds  = (const float*)d_in[1];
    const float* vd    = (const float*)d_in[2];
    const float* table = (const float*)d_in[3];
    const float* dw1   = (const float*)d_in[4];
    const float* db1   = (const float*)d_in[5];
    const float* dw2   = (const float*)d_in[6];
    const float* db2   = (const float*)d_in[7];
    const float* vw0   = (const float*)d_in[8];
    const float* vb0   = (const float*)d_in[9];
    const float* vw1   = (const float*)d_in[10];
    const float* vb1   = (const float*)d_in[11];
    const float* rw    = (const float*)d_in[12];
    const float* rb    = (const float*)d_in[13];
    float* out = (float*)d_out;

    cudaFuncSetAttribute(mlp_mma_kernel, cudaFuncAttributeMaxDynamicSharedMemorySize, SM_TOTAL);

    prep_kernel<<<(PK_TOTAL_H2 + 255) / 256, 256>>>(dw1, dw2, vw0, vw1);

    dim3 g1((RS_TOTAL + 127) / 128, NUM_LEVELS);
    grid_encode_kernel<<<g1, 128>>>(means, stds, (const float4*)table);

    mlp_mma_kernel<<<RS_TOTAL / 128, 512, SM_TOTAL>>>(vd, db1, db2, vb0, vb1, rw, rb, out);
}